// round 2
// baseline (speedup 1.0000x reference)
#include <cuda_runtime.h>
#include <cuda_bf16.h>
#include <mma.h>
#include <cstdint>
#include <cstddef>

using namespace nvcuda;

#define BATCH 8192
#define INF   784
#define HID   4096
#define OUTF  10
#define KP    832           // K padded to 26 chunks of 32
#define NCHUNKS 26

// ---------------------------------------------------------------------------
// Static device scratch (no runtime allocation allowed)
// ---------------------------------------------------------------------------
__device__ __nv_bfloat16 g_A[2ull * BATCH * KP];   // plane0 = hi, plane1 = lo  (54.5 MB)
__device__ __nv_bfloat16 g_Bm[(size_t)HID * KP];   // sign(W1), zero-padded      (6.8 MB)
__device__ float g_part[64ull * BATCH * OUTF];     // [ntile*2+half][batch][10]  (21 MB)

// ---------------------------------------------------------------------------
// Prep: split x into bf16 hi/lo planes; binarize W1. Both zero-pad K to 832.
// ---------------------------------------------------------------------------
__global__ void prep_x_kernel(const float* __restrict__ x) {
    int idx = blockIdx.x * blockDim.x + threadIdx.x;
    if (idx >= BATCH * KP) return;
    int m = idx / KP, k = idx - m * KP;
    float v = (k < INF) ? x[m * INF + k] : 0.0f;
    __nv_bfloat16 hi = __float2bfloat16(v);
    float lo = v - __bfloat162float(hi);
    g_A[idx] = hi;
    g_A[(size_t)BATCH * KP + idx] = __float2bfloat16(lo);
}

__global__ void prep_w_kernel(const float* __restrict__ W1) {
    int idx = blockIdx.x * blockDim.x + threadIdx.x;
    if (idx >= HID * KP) return;
    int r = idx / KP, k = idx - r * KP;
    float v = (k < INF) ? W1[r * INF + k] : 0.0f;
    float s = (v > 0.0f) ? 1.0f : ((v < 0.0f) ? -1.0f : 0.0f);
    g_Bm[idx] = __float2bfloat16(s);
}

// ---------------------------------------------------------------------------
// GEMM1 (x * sign(W1)^T via bf16 hi/lo split) + fused bias/clip/layer-2
// CTA tile 128x128, 8 warps of 64x32, double-buffered cp.async, K-chunk 32.
//
// Dynamic smem layout:
//   mainloop: Ash [2 stages][2 planes][128][40] bf16  @0      (40960 B)
//             Bsh [2 stages][128][40]            bf16 @40960  (20480 B)
//   epilogue: Csh [128][132] f32 @0 (67584 B)  -- reuses mainloop region
//   always  : W2sh [128][12] f32 @67584 (6144 B), b1sh [128] f32 @73728 (512 B)
// total 74240 B
// ---------------------------------------------------------------------------
#define SMEM_DYN 74240

__global__ __launch_bounds__(256, 2)
void gemm1_kernel(const float* __restrict__ b1g, const float* __restrict__ W2g) {
    extern __shared__ unsigned char smem[];
    __nv_bfloat16* Ash = (__nv_bfloat16*)smem;
    __nv_bfloat16* Bsh = (__nv_bfloat16*)(smem + 40960);
    float* Csh  = (float*)smem;
    float* W2sh = (float*)(smem + 67584);
    float* b1sh = (float*)(smem + 73728);

    const int tid = threadIdx.x;
    const int wid = tid >> 5;
    const int m0 = blockIdx.y * 128;
    const int n0 = blockIdx.x * 128;
    const int wm = wid & 1;   // 2 m-tiles of 64
    const int wn = wid >> 1;  // 4 n-tiles of 32

    // Preload W2/b1 tiles (region disjoint from mainloop buffers)
    for (int i = tid; i < 128 * OUTF; i += 256) {
        int n = i / OUTF, o = i - n * OUTF;
        W2sh[n * 12 + o] = W2g[o * HID + n0 + n];
    }
    if (tid < 128) b1sh[tid] = b1g[n0 + tid];

    wmma::fragment<wmma::accumulator, 16, 16, 16, float> acc[4][2];
    #pragma unroll
    for (int i = 0; i < 4; i++)
        #pragma unroll
        for (int j = 0; j < 2; j++) wmma::fill_fragment(acc[i][j], 0.0f);

    // Stage loader: 1024 x 16B for A (2 planes), 512 x 16B for B
    auto issue_stage = [&](int c) {
        const int s = c & 1;
        const int k0 = c * 32;
        for (int i = tid; i < 1536; i += 256) {
            uint32_t dst;
            const __nv_bfloat16* src;
            if (i < 1024) {
                int plane = i >> 9, r = (i >> 2) & 127, seg = i & 3;
                dst = (uint32_t)__cvta_generic_to_shared(
                    &Ash[((s * 2 + plane) * 128 + r) * 40 + seg * 8]);
                src = &g_A[(plane * (size_t)BATCH + (m0 + r)) * KP + k0 + seg * 8];
            } else {
                int j = i - 1024, r = j >> 2, seg = j & 3;
                dst = (uint32_t)__cvta_generic_to_shared(
                    &Bsh[(s * 128 + r) * 40 + seg * 8]);
                src = &g_Bm[(size_t)(n0 + r) * KP + k0 + seg * 8];
            }
            asm volatile("cp.async.cg.shared.global [%0], [%1], 16;" :: "r"(dst), "l"(src));
        }
        asm volatile("cp.async.commit_group;" ::: "memory");
    };

    issue_stage(0);

    for (int c = 0; c < NCHUNKS; c++) {
        const int s = c & 1;
        if (c + 1 < NCHUNKS) {
            issue_stage(c + 1);
            asm volatile("cp.async.wait_group 1;" ::: "memory");
        } else {
            asm volatile("cp.async.wait_group 0;" ::: "memory");
        }
        __syncthreads();

        #pragma unroll
        for (int kf = 0; kf < 2; kf++) {
            wmma::fragment<wmma::matrix_b, 16, 16, 16, __nv_bfloat16, wmma::col_major> bfr[2];
            #pragma unroll
            for (int nf = 0; nf < 2; nf++)
                wmma::load_matrix_sync(bfr[nf],
                    &Bsh[(s * 128 + wn * 32 + nf * 16) * 40 + kf * 16], 40);
            #pragma unroll
            for (int plane = 0; plane < 2; plane++) {   // hi then lo, B frags reused
                #pragma unroll
                for (int mf = 0; mf < 4; mf++) {
                    wmma::fragment<wmma::matrix_a, 16, 16, 16, __nv_bfloat16, wmma::row_major> afr;
                    wmma::load_matrix_sync(afr,
                        &Ash[((s * 2 + plane) * 128 + wm * 64 + mf * 16) * 40 + kf * 16], 40);
                    #pragma unroll
                    for (int nf = 0; nf < 2; nf++)
                        wmma::mma_sync(acc[mf][nf], afr, bfr[nf], acc[mf][nf]);
                }
            }
        }
        __syncthreads();   // all warps done with buffer before it is re-filled
    }

    // ---- Epilogue: stage C, bias+clip, contract with W2 (deterministic) ----
    #pragma unroll
    for (int mf = 0; mf < 4; mf++)
        #pragma unroll
        for (int nf = 0; nf < 2; nf++)
            wmma::store_matrix_sync(
                &Csh[(wm * 64 + mf * 16) * 132 + wn * 32 + nf * 16],
                acc[mf][nf], 132, wmma::mem_row_major);
    __syncthreads();

    const int b = tid & 127;
    const int half = tid >> 7;   // each half of the n-range -> its own partial slice
    float a[OUTF];
    #pragma unroll
    for (int o = 0; o < OUTF; o++) a[o] = 0.0f;

    const int nbeg = half * 64;
    for (int n = nbeg; n < nbeg + 64; n++) {
        float cv = Csh[b * 132 + n] + b1sh[n];
        cv = fminf(1.0f, fmaxf(-1.0f, cv));
        const float* w = &W2sh[n * 12];
        #pragma unroll
        for (int o = 0; o < OUTF; o++) a[o] += cv * w[o];
    }

    const int slice = blockIdx.x * 2 + half;   // 64 slices total
    float* dst = &g_part[((size_t)slice * BATCH + m0 + b) * OUTF];
    #pragma unroll
    for (int o = 0; o < OUTF; o++) dst[o] = a[o];
}

// ---------------------------------------------------------------------------
// Final reduce: out[b][o] = b2[o] + sum over 64 partial slices
// ---------------------------------------------------------------------------
__global__ void reduce_kernel(const float* __restrict__ b2, float* __restrict__ out) {
    int idx = blockIdx.x * blockDim.x + threadIdx.x;
    if (idx >= BATCH * OUTF) return;
    int o = idx % OUTF;
    float s = b2[o];
    #pragma unroll
    for (int p = 0; p < 64; p++)
        s += g_part[(size_t)p * BATCH * OUTF + idx];
    out[idx] = s;
}

// ---------------------------------------------------------------------------
extern "C" void kernel_launch(void* const* d_in, const int* in_sizes, int n_in,
                              void* d_out, int out_size) {
    (void)in_sizes; (void)n_in; (void)out_size;
    const float* x  = (const float*)d_in[0];
    const float* W1 = (const float*)d_in[1];
    const float* b1 = (const float*)d_in[2];
    const float* W2 = (const float*)d_in[3];
    const float* b2 = (const float*)d_in[4];
    float* out = (float*)d_out;

    cudaFuncSetAttribute(gemm1_kernel,
                         cudaFuncAttributeMaxDynamicSharedMemorySize, SMEM_DYN);

    prep_x_kernel<<<(BATCH * KP + 255) / 256, 256>>>(x);
    prep_w_kernel<<<(HID * KP + 255) / 256, 256>>>(W1);
    gemm1_kernel<<<dim3(HID / 128, BATCH / 128), 256, SMEM_DYN>>>(b1, W2);
    reduce_kernel<<<(BATCH * OUTF + 255) / 256, 256>>>(b2, out);
}

// round 4
// speedup vs baseline: 1.0494x; 1.0494x over previous
#include <cuda_runtime.h>
#include <mma.h>
#include <cstdint>
#include <cstddef>

using namespace nvcuda;

#define BATCH 8192
#define INF   784
#define HID   4096
#define OUTF  10
#define KP    832            // 13 chunks of 64
#define NCH   13

#define TMT 128              // CTA tile M
#define TNT 128              // CTA tile N

// int8 quantization scales: x = a1/16 + a2/4064 + eps, |eps| <= 1/8128
#define S1_INV 0.0625f
#define S2_INV (1.0f / 4064.0f)

// SMEM layout (bytes). Stage: Ahi 128x80 | Alo 128x80 | B 128x80 (int8)
#define ROWB      80u
#define STAGE_B   (3u * 128u * ROWB)          // 30720
#define SOFF_STG  0u
#define SOFF_C1   0u                          // epilogue reuses stage region
#define SOFF_C2   67584u                      // 128*132*4
#define SOFF_W2   135168u                     // [10][128] f32
#define SOFF_B1   140288u                     // [128] f32
#define SMEM_DYN  140800u

// ---------------------------------------------------------------------------
// Static scratch
// ---------------------------------------------------------------------------
__device__ signed char g_A8[2ull * BATCH * KP];    // plane0 (x*16), plane1 (resid*4064)
__device__ signed char g_S8[(size_t)HID * KP];     // sign(W1)
__device__ float g_part[128ull * BATCH * OUTF];    // [slice][batch][10]  (41.9 MB)

// ---------------------------------------------------------------------------
// Prep
// ---------------------------------------------------------------------------
__global__ void prep_x_kernel(const float* __restrict__ x) {
    int idx = blockIdx.x * blockDim.x + threadIdx.x;
    if (idx >= BATCH * KP) return;
    int m = idx / KP, k = idx - m * KP;
    float v = (k < INF) ? x[m * INF + k] : 0.0f;
    float a1 = rintf(v * 16.0f);
    float r  = v - a1 * S1_INV;
    float a2 = rintf(r * 4064.0f);
    g_A8[idx] = (signed char)(int)a1;
    g_A8[(size_t)BATCH * KP + idx] = (signed char)(int)a2;
}

__global__ void prep_w_kernel(const float* __restrict__ W1) {
    int idx = blockIdx.x * blockDim.x + threadIdx.x;
    if (idx >= HID * KP) return;
    int r = idx / KP, k = idx - r * KP;
    float v = (k < INF) ? W1[r * INF + k] : 0.0f;
    g_S8[idx] = (signed char)((v > 0.0f) ? 1 : ((v < 0.0f) ? -1 : 0));
}

// ---------------------------------------------------------------------------
// GEMM1: int8 wmma, CTA 128x128, 16 warps (8 per plane), warp tile 64x32,
// K-chunk 64, 3-stage cp.async pipeline, fused bias/clip/W2 epilogue.
// ---------------------------------------------------------------------------
__global__ __launch_bounds__(512, 1)
void gemm1_kernel(const float* __restrict__ b1g, const float* __restrict__ W2g) {
    extern __shared__ unsigned char smem[];
    signed char* stg_base = (signed char*)smem;
    float* C1   = (float*)(smem + SOFF_C1);
    float* C2   = (float*)(smem + SOFF_C2);
    float* W2sh = (float*)(smem + SOFF_W2);
    float* b1sh = (float*)(smem + SOFF_B1);

    const int tid  = threadIdx.x;
    const int wid  = tid >> 5;
    const int m0 = blockIdx.y * TMT;
    const int n0 = blockIdx.x * TNT;

    const int plane = wid >> 3;        // 0: hi plane, 1: lo plane
    const int wsub  = wid & 7;
    const int wm    = wsub & 1;        // 2 m-tiles of 64
    const int wn    = wsub >> 1;       // 4 n-tiles of 32

    // epilogue constants (disjoint smem region)
    for (int i = tid; i < OUTF * 128; i += 512) {
        int o = i >> 7, n = i & 127;
        W2sh[o * 128 + n] = W2g[o * HID + n0 + n];
    }
    if (tid < 128) b1sh[tid] = b1g[n0 + tid];

    wmma::fragment<wmma::accumulator, 16, 16, 16, int> acc[4][2];
    #pragma unroll
    for (int i = 0; i < 4; i++)
        #pragma unroll
        for (int j = 0; j < 2; j++) wmma::fill_fragment(acc[i][j], 0);

    // stage loader: 1536 x 16B (A both planes 1024, B 512); 3 per thread
    auto issue_loads = [&](int c) {
        signed char* stg = stg_base + (size_t)(c % 3) * STAGE_B;
        const int k0 = c * 64;
        #pragma unroll
        for (int t = 0; t < 3; t++) {
            int i = t * 512 + tid;
            uint32_t dst;
            const signed char* src;
            if (i < 1024) {
                int pl = i >> 9, row = (i >> 2) & 127, seg = i & 3;
                dst = (uint32_t)__cvta_generic_to_shared(
                    stg + (uint32_t)pl * (128u * ROWB) + row * ROWB + seg * 16);
                src = &g_A8[((size_t)pl * BATCH + m0 + row) * KP + k0 + seg * 16];
            } else {
                int j = i - 1024, row = j >> 2, seg = j & 3;
                dst = (uint32_t)__cvta_generic_to_shared(
                    stg + 2u * (128u * ROWB) + row * ROWB + seg * 16);
                src = &g_S8[(size_t)(n0 + row) * KP + k0 + seg * 16];
            }
            asm volatile("cp.async.cg.shared.global [%0], [%1], 16;" :: "r"(dst), "l"(src));
        }
        asm volatile("cp.async.commit_group;" ::: "memory");
    };

    issue_loads(0);
    issue_loads(1);
    issue_loads(2);

    for (int c = 0; c < NCH; c++) {
        if (c <= NCH - 3)      asm volatile("cp.async.wait_group 2;" ::: "memory");
        else if (c == NCH - 2) asm volatile("cp.async.wait_group 1;" ::: "memory");
        else                   asm volatile("cp.async.wait_group 0;" ::: "memory");
        __syncthreads();

        const signed char* stg = stg_base + (size_t)(c % 3) * STAGE_B;
        const signed char* Ash = stg + (size_t)plane * (128 * ROWB);
        const signed char* Bsh = stg + 2 * (128 * ROWB);

        #pragma unroll
        for (int kf = 0; kf < 4; kf++) {
            wmma::fragment<wmma::matrix_b, 16, 16, 16, signed char, wmma::col_major> bfr[2];
            #pragma unroll
            for (int nf = 0; nf < 2; nf++)
                wmma::load_matrix_sync(bfr[nf],
                    Bsh + (wn * 32 + nf * 16) * ROWB + kf * 16, ROWB);
            #pragma unroll
            for (int mf = 0; mf < 4; mf++) {
                wmma::fragment<wmma::matrix_a, 16, 16, 16, signed char, wmma::row_major> afr;
                wmma::load_matrix_sync(afr,
                    Ash + (wm * 64 + mf * 16) * ROWB + kf * 16, ROWB);
                #pragma unroll
                for (int nf = 0; nf < 2; nf++)
                    wmma::mma_sync(acc[mf][nf], afr, bfr[nf], acc[mf][nf]);
            }
        }
        __syncthreads();
        if (c + 3 < NCH) issue_loads(c + 3);
    }
    __syncthreads();   // all MMA consumers done before stage region becomes C1

    // ---- epilogue: scale per plane into separate buffers ----
    const float sc = plane ? S2_INV : S1_INV;
    float* Cdst = plane ? C2 : C1;
    #pragma unroll
    for (int mf = 0; mf < 4; mf++) {
        #pragma unroll
        for (int nf = 0; nf < 2; nf++) {
            wmma::fragment<wmma::accumulator, 16, 16, 16, float> f;
            #pragma unroll
            for (int e = 0; e < f.num_elements; e++)
                f.x[e] = (float)acc[mf][nf].x[e] * sc;
            wmma::store_matrix_sync(
                &Cdst[(wm * 64 + mf * 16) * 132 + wn * 32 + nf * 16],
                f, 132, wmma::mem_row_major);
        }
    }
    __syncthreads();

    // combine + bias + clip + W2 contraction; 512 thr = 128 rows x 4 col-quarters
    const int row = tid & 127;
    const int q   = tid >> 7;           // 0..3, cols [32q, 32q+32)
    float a[OUTF];
    #pragma unroll
    for (int o = 0; o < OUTF; o++) a[o] = 0.0f;

    const int nbeg = q * 32;
    #pragma unroll 4
    for (int n = nbeg; n < nbeg + 32; n++) {
        float h = C1[row * 132 + n] + C2[row * 132 + n] + b1sh[n];
        h = fminf(1.0f, fmaxf(-1.0f, h));
        #pragma unroll
        for (int o = 0; o < OUTF; o++) a[o] += h * W2sh[o * 128 + n];
    }

    const int slice = blockIdx.x * 4 + q;     // 128 slices
    float* dst = &g_part[((size_t)slice * BATCH + m0 + row) * OUTF];
    #pragma unroll
    for (int o = 0; o < OUTF; o++) dst[o] = a[o];
}

// ---------------------------------------------------------------------------
// Final reduce: out[b][o] = b2[o] + sum of 128 slices
// ---------------------------------------------------------------------------
__global__ void reduce_kernel(const float* __restrict__ b2, float* __restrict__ out) {
    int idx = blockIdx.x * blockDim.x + threadIdx.x;
    if (idx >= BATCH * OUTF) return;
    int o = idx % OUTF;
    float s = b2[o];
    #pragma unroll
    for (int p = 0; p < 128; p++)
        s += g_part[(size_t)p * BATCH * OUTF + idx];
    out[idx] = s;
}

// ---------------------------------------------------------------------------
extern "C" void kernel_launch(void* const* d_in, const int* in_sizes, int n_in,
                              void* d_out, int out_size) {
    (void)in_sizes; (void)n_in; (void)out_size;
    const float* x  = (const float*)d_in[0];
    const float* W1 = (const float*)d_in[1];
    const float* b1 = (const float*)d_in[2];
    const float* W2 = (const float*)d_in[3];
    const float* b2 = (const float*)d_in[4];
    float* out = (float*)d_out;

    cudaFuncSetAttribute(gemm1_kernel,
                         cudaFuncAttributeMaxDynamicSharedMemorySize, SMEM_DYN);

    prep_x_kernel<<<(BATCH * KP + 255) / 256, 256>>>(x);
    prep_w_kernel<<<(HID * KP + 255) / 256, 256>>>(W1);
    gemm1_kernel<<<dim3(HID / TNT, BATCH / TMT), 512, SMEM_DYN>>>(b1, W2);
    reduce_kernel<<<(BATCH * OUTF + 255) / 256, 256>>>(b2, out);
}

// round 5
// speedup vs baseline: 1.6012x; 1.5258x over previous
#include <cuda_runtime.h>
#include <cstdint>
#include <cstddef>

#define BATCH 8192
#define INF   784
#define HID   4096
#define OUTF  10
#define KP    832            // 13 chunks of 64
#define NCH   13

#define TMT 128
#define TNT 128

// x = a1/16 + a2/4064 + eps, |eps| <= 1/8128
#define S1_INV 0.0625f
#define S2_INV (1.0f / 4064.0f)

// SMEM: stage = Ahi[128][80] | Alo[128][80] | B[128][80] int8
#define ROWB     80u
#define PL_B     10240u                     // 128*80
#define STAGE_B  30720u
#define SOFF_W2  92160u                     // 3*STAGE_B
#define SOFF_B1  97280u
#define SMEM_DYN 98304u

// ---------------------------------------------------------------------------
__device__ signed char g_A8[2ull * BATCH * KP];
__device__ signed char g_S8[(size_t)HID * KP];
__device__ float g_part[128ull * BATCH * OUTF];

// ---------------------------------------------------------------------------
__device__ __forceinline__ uint32_t smem_u32(const void* p) {
    uint32_t a;
    asm("{ .reg .u64 t; cvta.to.shared.u64 t, %1; cvt.u32.u64 %0, t; }"
        : "=r"(a) : "l"(p));
    return a;
}

__device__ __forceinline__ void ldsm_x4(uint32_t& r0, uint32_t& r1,
                                        uint32_t& r2, uint32_t& r3, uint32_t a) {
    asm volatile("ldmatrix.sync.aligned.m8n8.x4.shared.b16 {%0,%1,%2,%3}, [%4];"
                 : "=r"(r0), "=r"(r1), "=r"(r2), "=r"(r3) : "r"(a));
}

__device__ __forceinline__ void mma_s8(int* d, uint32_t a0, uint32_t a1,
                                       uint32_t a2, uint32_t a3,
                                       uint32_t b0, uint32_t b1) {
    asm volatile(
        "mma.sync.aligned.m16n8k32.row.col.s32.s8.s8.s32 "
        "{%0,%1,%2,%3}, {%4,%5,%6,%7}, {%8,%9}, {%0,%1,%2,%3};"
        : "+r"(d[0]), "+r"(d[1]), "+r"(d[2]), "+r"(d[3])
        : "r"(a0), "r"(a1), "r"(a2), "r"(a3), "r"(b0), "r"(b1));
}

// ---------------------------------------------------------------------------
__global__ void prep_x_kernel(const float* __restrict__ x) {
    int idx = blockIdx.x * blockDim.x + threadIdx.x;
    if (idx >= BATCH * KP) return;
    int m = idx / KP, k = idx - m * KP;
    float v = (k < INF) ? x[m * INF + k] : 0.0f;
    float a1 = rintf(v * 16.0f);
    float r  = v - a1 * S1_INV;
    float a2 = rintf(r * 4064.0f);
    g_A8[idx] = (signed char)(int)a1;
    g_A8[(size_t)BATCH * KP + idx] = (signed char)(int)a2;
}

__global__ void prep_w_kernel(const float* __restrict__ W1) {
    int idx = blockIdx.x * blockDim.x + threadIdx.x;
    if (idx >= HID * KP) return;
    int r = idx / KP, k = idx - r * KP;
    float v = (k < INF) ? W1[r * INF + k] : 0.0f;
    g_S8[idx] = (signed char)((v > 0.0f) ? 1 : ((v < 0.0f) ? -1 : 0));
}

// ---------------------------------------------------------------------------
// GEMM1: s8 mma.m16n8k32, CTA 128x128, 16 warps x (32x32 tile, both planes)
// ---------------------------------------------------------------------------
__global__ __launch_bounds__(512, 1)
void gemm1_kernel(const float* __restrict__ b1g, const float* __restrict__ W2g) {
    extern __shared__ unsigned char smem[];
    signed char* stg_base = (signed char*)smem;
    float* Csh  = (float*)smem;                  // epilogue reuse of stage region
    float* W2sh = (float*)(smem + SOFF_W2);
    float* b1sh = (float*)(smem + SOFF_B1);
    const uint32_t sb = smem_u32(smem);

    const int tid = threadIdx.x;
    const int wid = tid >> 5;
    const int lane = tid & 31;
    const int m0 = blockIdx.y * TMT;
    const int n0 = blockIdx.x * TNT;
    const int wm = wid & 3;        // 4 m-subtiles of 32
    const int wn = wid >> 2;       // 4 n-subtiles of 32

    for (int i = tid; i < OUTF * 128; i += 512) {
        int o = i >> 7, n = i & 127;
        W2sh[o * 128 + n] = W2g[o * HID + n0 + n];
    }
    if (tid < 128) b1sh[tid] = b1g[n0 + tid];

    // ldmatrix per-lane base offsets (within a stage)
    const int l15 = lane & 15;
    uint32_t aoff[2][2];
    #pragma unroll
    for (int pl = 0; pl < 2; pl++)
        #pragma unroll
        for (int mf = 0; mf < 2; mf++)
            aoff[pl][mf] = (uint32_t)pl * PL_B
                         + (uint32_t)(wm * 32 + mf * 16 + l15) * ROWB
                         + ((uint32_t)(lane >> 4) << 4);
    uint32_t boff[2];
    #pragma unroll
    for (int np = 0; np < 2; np++)
        boff[np] = 2u * PL_B
                 + (uint32_t)(wn * 32 + np * 16 + ((lane >> 4) << 3) + (lane & 7)) * ROWB
                 + (((uint32_t)(lane >> 3) & 1u) << 4);

    int acc[2][2][4][4];
    #pragma unroll
    for (int pl = 0; pl < 2; pl++)
        #pragma unroll
        for (int mf = 0; mf < 2; mf++)
            #pragma unroll
            for (int n8 = 0; n8 < 4; n8++)
                #pragma unroll
                for (int e = 0; e < 4; e++) acc[pl][mf][n8][e] = 0;

    auto issue_loads = [&](int c) {
        signed char* stg = stg_base + (size_t)(c % 3) * STAGE_B;
        const int k0 = c * 64;
        #pragma unroll
        for (int t = 0; t < 3; t++) {
            int i = t * 512 + tid;
            uint32_t dst;
            const signed char* src;
            if (i < 1024) {
                int pl = i >> 9, row = (i >> 2) & 127, seg = i & 3;
                dst = (uint32_t)__cvta_generic_to_shared(
                    stg + (uint32_t)pl * PL_B + row * ROWB + seg * 16);
                src = &g_A8[((size_t)pl * BATCH + m0 + row) * KP + k0 + seg * 16];
            } else {
                int j = i - 1024, row = j >> 2, seg = j & 3;
                dst = (uint32_t)__cvta_generic_to_shared(
                    stg + 2u * PL_B + row * ROWB + seg * 16);
                src = &g_S8[(size_t)(n0 + row) * KP + k0 + seg * 16];
            }
            asm volatile("cp.async.cg.shared.global [%0], [%1], 16;" :: "r"(dst), "l"(src));
        }
        asm volatile("cp.async.commit_group;" ::: "memory");
    };

    issue_loads(0);
    issue_loads(1);
    issue_loads(2);

    for (int c = 0; c < NCH; c++) {
        if (c <= NCH - 3)      asm volatile("cp.async.wait_group 2;" ::: "memory");
        else if (c == NCH - 2) asm volatile("cp.async.wait_group 1;" ::: "memory");
        else                   asm volatile("cp.async.wait_group 0;" ::: "memory");
        __syncthreads();

        const uint32_t stg = sb + (uint32_t)(c % 3) * STAGE_B;
        #pragma unroll
        for (int kb = 0; kb < 64; kb += 32) {
            uint32_t b[8];
            ldsm_x4(b[0], b[1], b[2], b[3], stg + boff[0] + kb);
            ldsm_x4(b[4], b[5], b[6], b[7], stg + boff[1] + kb);
            #pragma unroll
            for (int pl = 0; pl < 2; pl++) {
                #pragma unroll
                for (int mf = 0; mf < 2; mf++) {
                    uint32_t a0, a1, a2, a3;
                    ldsm_x4(a0, a1, a2, a3, stg + aoff[pl][mf] + kb);
                    mma_s8(acc[pl][mf][0], a0, a1, a2, a3, b[0], b[1]);
                    mma_s8(acc[pl][mf][1], a0, a1, a2, a3, b[2], b[3]);
                    mma_s8(acc[pl][mf][2], a0, a1, a2, a3, b[4], b[5]);
                    mma_s8(acc[pl][mf][3], a0, a1, a2, a3, b[6], b[7]);
                }
            }
        }
        __syncthreads();
        if (c + 3 < NCH) issue_loads(c + 3);
    }
    __syncthreads();   // stage region now free -> becomes Csh

    // ---- combine planes in registers, store h tile to smem ----
    const int g  = lane >> 2;
    const int tg = lane & 3;
    #pragma unroll
    for (int mf = 0; mf < 2; mf++) {
        #pragma unroll
        for (int n8 = 0; n8 < 4; n8++) {
            const int* Ah = acc[0][mf][n8];
            const int* Al = acc[1][mf][n8];
            int row0 = wm * 32 + mf * 16 + g;
            int col  = wn * 32 + n8 * 8 + 2 * tg;
            Csh[row0 * 132 + col]           = (float)Ah[0] * S1_INV + (float)Al[0] * S2_INV;
            Csh[row0 * 132 + col + 1]       = (float)Ah[1] * S1_INV + (float)Al[1] * S2_INV;
            Csh[(row0 + 8) * 132 + col]     = (float)Ah[2] * S1_INV + (float)Al[2] * S2_INV;
            Csh[(row0 + 8) * 132 + col + 1] = (float)Ah[3] * S1_INV + (float)Al[3] * S2_INV;
        }
    }
    __syncthreads();

    // ---- bias + clip + W2 contraction (deterministic partials) ----
    const int row = tid & 127;
    const int q   = tid >> 7;          // 4 col-quarters of 32
    float a[OUTF];
    #pragma unroll
    for (int o = 0; o < OUTF; o++) a[o] = 0.0f;

    const int nbeg = q * 32;
    #pragma unroll 4
    for (int n = nbeg; n < nbeg + 32; n++) {
        float h = Csh[row * 132 + n] + b1sh[n];
        h = fminf(1.0f, fmaxf(-1.0f, h));
        #pragma unroll
        for (int o = 0; o < OUTF; o++) a[o] += h * W2sh[o * 128 + n];
    }

    const int slice = blockIdx.x * 4 + q;   // 128 slices
    float* dst = &g_part[((size_t)slice * BATCH + m0 + row) * OUTF];
    #pragma unroll
    for (int o = 0; o < OUTF; o++) dst[o] = a[o];
}

// ---------------------------------------------------------------------------
__global__ void reduce_kernel(const float* __restrict__ b2, float* __restrict__ out) {
    int idx = blockIdx.x * blockDim.x + threadIdx.x;
    if (idx >= BATCH * OUTF) return;
    int o = idx % OUTF;
    float s = b2[o];
    #pragma unroll
    for (int p = 0; p < 128; p++)
        s += g_part[(size_t)p * BATCH * OUTF + idx];
    out[idx] = s;
}

// ---------------------------------------------------------------------------
extern "C" void kernel_launch(void* const* d_in, const int* in_sizes, int n_in,
                              void* d_out, int out_size) {
    (void)in_sizes; (void)n_in; (void)out_size;
    const float* x  = (const float*)d_in[0];
    const float* W1 = (const float*)d_in[1];
    const float* b1 = (const float*)d_in[2];
    const float* W2 = (const float*)d_in[3];
    const float* b2 = (const float*)d_in[4];
    float* out = (float*)d_out;

    cudaFuncSetAttribute(gemm1_kernel,
                         cudaFuncAttributeMaxDynamicSharedMemorySize, SMEM_DYN);

    prep_x_kernel<<<(BATCH * KP + 255) / 256, 256>>>(x);
    prep_w_kernel<<<(HID * KP + 255) / 256, 256>>>(W1);
    gemm1_kernel<<<dim3(HID / TNT, BATCH / TMT), 512, SMEM_DYN>>>(b1, W2);
    reduce_kernel<<<(BATCH * OUTF + 255) / 256, 256>>>(b2, out);
}

// round 6
// speedup vs baseline: 1.6579x; 1.0354x over previous
#include <cuda_runtime.h>
#include <cstdint>
#include <cstddef>

#define BATCH 8192
#define INF   784
#define HID   4096
#define OUTF  10
#define KP    832            // 13 chunks of 64
#define NCH   13

#define TMT 128
#define TNT 128

// x = a1/16 + a2/4064 + eps, |eps| <= 1/8128
#define S1_INV 0.0625f
#define S2_INV (1.0f / 4064.0f)

// chunk-major gmem blocks
#define CHUNK_A (BATCH * 64)         // 524288 bytes per (plane, chunk)
#define CHUNK_B (HID * 64)           // 262144 bytes per chunk

// SMEM: 4 stages x (Ahi 8K | Alo 8K | B 8K)
#define STAGE_B  24576u
#define NSTG     4
#define SOFF_W2  98304u              // [10][128] f32
#define SOFF_B1  103424u             // [128] f32
#define SOFF_BAR 103936u             // 4 mbarriers
#define SMEM_DYN 104960u

// ---------------------------------------------------------------------------
__device__ signed char g_A8c[2ull * NCH * CHUNK_A];   // [plane][chunk][swizzled]
__device__ signed char g_S8c[(size_t)NCH * CHUNK_B];  // [chunk][swizzled]
__device__ float g_part[128ull * BATCH * OUTF];

// ---------------------------------------------------------------------------
__device__ __forceinline__ uint32_t smem_u32(const void* p) {
    uint32_t a;
    asm("{ .reg .u64 t; cvta.to.shared.u64 t, %1; cvt.u32.u64 %0, t; }"
        : "=r"(a) : "l"(p));
    return a;
}

// SW128-style offset of (row, kbyte) within one chunk block: rows paired into
// 128B lines, 16B segments XOR-permuted by line index.
__device__ __forceinline__ uint32_t chunk_off(int row, int kk) {
    uint32_t line = (uint32_t)(row >> 1);
    uint32_t col  = (((uint32_t)(row & 1)) << 6) | (uint32_t)kk;
    return (line << 7) | (col ^ ((line & 7u) << 4));
}

__device__ __forceinline__ void ldsm_x4(uint32_t& r0, uint32_t& r1,
                                        uint32_t& r2, uint32_t& r3, uint32_t a) {
    asm volatile("ldmatrix.sync.aligned.m8n8.x4.shared.b16 {%0,%1,%2,%3}, [%4];"
                 : "=r"(r0), "=r"(r1), "=r"(r2), "=r"(r3) : "r"(a));
}

__device__ __forceinline__ void mma_s8(int* d, uint32_t a0, uint32_t a1,
                                       uint32_t a2, uint32_t a3,
                                       uint32_t b0, uint32_t b1) {
    asm volatile(
        "mma.sync.aligned.m16n8k32.row.col.s32.s8.s8.s32 "
        "{%0,%1,%2,%3}, {%4,%5,%6,%7}, {%8,%9}, {%0,%1,%2,%3};"
        : "+r"(d[0]), "+r"(d[1]), "+r"(d[2]), "+r"(d[3])
        : "r"(a0), "r"(a1), "r"(a2), "r"(a3), "r"(b0), "r"(b1));
}

#define MBAR_INIT(a, c) \
    asm volatile("mbarrier.init.shared.b64 [%0], %1;" :: "r"(a), "r"(c) : "memory")
#define MBAR_EXPECT(a, bytes) \
    asm volatile("mbarrier.arrive.expect_tx.shared.b64 _, [%0], %1;" \
                 :: "r"(a), "r"(bytes) : "memory")
#define BULK_CP(dst, src, size, mbar) \
    asm volatile("cp.async.bulk.shared::cluster.global.mbarrier::complete_tx::bytes " \
                 "[%0], [%1], %2, [%3];" \
                 :: "r"(dst), "l"(src), "r"(size), "r"(mbar) : "memory")

#define MBAR_WAIT(a, par) do {                                                 \
    uint32_t _m = (a), _p = (par), _d;                                         \
    asm volatile("{\n\t.reg .pred p;\n\t"                                      \
        "mbarrier.try_wait.parity.acquire.cta.shared::cta.b64 p, [%1], %2;\n\t"\
        "selp.b32 %0, 1, 0, p;\n\t}" : "=r"(_d) : "r"(_m), "r"(_p) : "memory");\
    if (!_d) {                                                                 \
        asm volatile("{\n\t.reg .pred P1;\n\t"                                 \
            "WL_%=:\n\t"                                                       \
            "mbarrier.try_wait.parity.acquire.cta.shared::cta.b64 P1, [%0], %1, 0x989680;\n\t" \
            "@P1 bra.uni WD_%=;\n\t"                                           \
            "bra.uni WL_%=;\n\t"                                               \
            "WD_%=:\n\t}" :: "r"(_m), "r"(_p) : "memory");                     \
    }                                                                          \
} while (0)

// ---------------------------------------------------------------------------
// Prep: quantize + scatter into chunk-major swizzled layout
// ---------------------------------------------------------------------------
__global__ void prep_x_kernel(const float* __restrict__ x) {
    int idx = blockIdx.x * blockDim.x + threadIdx.x;
    if (idx >= BATCH * KP) return;
    int m = idx / KP, k = idx - m * KP;
    float v = (k < INF) ? x[m * INF + k] : 0.0f;
    float a1 = rintf(v * 16.0f);
    float r  = v - a1 * S1_INV;
    float a2 = rintf(r * 4064.0f);
    int c = k >> 6, kk = k & 63;
    size_t o = (size_t)c * CHUNK_A + chunk_off(m, kk);
    g_A8c[o] = (signed char)(int)a1;
    g_A8c[(size_t)NCH * CHUNK_A + o] = (signed char)(int)a2;
}

__global__ void prep_w_kernel(const float* __restrict__ W1) {
    int idx = blockIdx.x * blockDim.x + threadIdx.x;
    if (idx >= HID * KP) return;
    int r = idx / KP, k = idx - r * KP;
    float v = (k < INF) ? W1[r * INF + k] : 0.0f;
    int c = k >> 6, kk = k & 63;
    g_S8c[(size_t)c * CHUNK_B + chunk_off(r, kk)] =
        (signed char)((v > 0.0f) ? 1 : ((v < 0.0f) ? -1 : 0));
}

// ---------------------------------------------------------------------------
// GEMM1: s8 mma.m16n8k32, CTA 128x128, 16 warps x 32x32 (both planes),
// 4-stage cp.async.bulk pipeline (3 bulk copies per K-chunk of 64).
// ---------------------------------------------------------------------------
__global__ __launch_bounds__(512, 1)
void gemm1_kernel(const float* __restrict__ b1g, const float* __restrict__ W2g) {
    extern __shared__ unsigned char smem[];
    float* Csh  = (float*)smem;                  // epilogue reuse of stage region
    float* W2sh = (float*)(smem + SOFF_W2);
    float* b1sh = (float*)(smem + SOFF_B1);
    const uint32_t sb = smem_u32(smem);

    const int tid = threadIdx.x;
    const int wid = tid >> 5;
    const int lane = tid & 31;
    const int m0 = blockIdx.y * TMT;
    const int n0 = blockIdx.x * TNT;
    const int wm = wid & 3;
    const int wn = wid >> 2;

    if (tid == 0) {
        #pragma unroll
        for (int s = 0; s < NSTG; s++) MBAR_INIT(sb + SOFF_BAR + s * 8, 1);
    }
    for (int i = tid; i < OUTF * 128; i += 512) {
        int o = i >> 7, n = i & 127;
        W2sh[o * 128 + n] = W2g[o * HID + n0 + n];
    }
    if (tid < 128) b1sh[tid] = b1g[n0 + tid];
    __syncthreads();

    auto issue = [&](int c) {
        const int s = c & 3;
        const uint32_t stg = sb + (uint32_t)s * STAGE_B;
        const uint32_t mb  = sb + SOFF_BAR + (uint32_t)s * 8;
        MBAR_EXPECT(mb, STAGE_B);
        const signed char* a0 = g_A8c + (size_t)c * CHUNK_A + (size_t)m0 * 64;
        const signed char* a1 = g_A8c + (size_t)(NCH + c) * CHUNK_A + (size_t)m0 * 64;
        const signed char* bb = g_S8c + (size_t)c * CHUNK_B + (size_t)n0 * 64;
        BULK_CP(stg,          a0, 8192u, mb);
        BULK_CP(stg + 8192u,  a1, 8192u, mb);
        BULK_CP(stg + 16384u, bb, 8192u, mb);
    };

    if (tid == 0) {
        issue(0); issue(1); issue(2); issue(3);
    }

    // per-lane ldmatrix (row, kbyte-base) components
    const int l15 = lane & 15;
    uint32_t a_line[2][2], a_xm[2][2], a_c0[2][2];
    #pragma unroll
    for (int pl = 0; pl < 2; pl++)
        #pragma unroll
        for (int mf = 0; mf < 2; mf++) {
            int r = wm * 32 + mf * 16 + l15;
            a_line[pl][mf] = (uint32_t)pl * 8192u + (((uint32_t)r >> 1) << 7);
            a_xm[pl][mf]   = (((uint32_t)(r >> 1) & 7u) << 4);
            a_c0[pl][mf]   = (((uint32_t)r & 1u) << 6) | (((uint32_t)lane >> 4) << 4);
        }
    uint32_t b_line[2], b_xm[2], b_c0[2];
    #pragma unroll
    for (int np = 0; np < 2; np++) {
        int r = wn * 32 + np * 16 + ((lane >> 4) << 3) + (lane & 7);
        b_line[np] = 16384u + (((uint32_t)r >> 1) << 7);
        b_xm[np]   = (((uint32_t)(r >> 1) & 7u) << 4);
        b_c0[np]   = (((uint32_t)r & 1u) << 6) | ((((uint32_t)lane >> 3) & 1u) << 4);
    }

    int acc[2][2][4][4];
    #pragma unroll
    for (int pl = 0; pl < 2; pl++)
        #pragma unroll
        for (int mf = 0; mf < 2; mf++)
            #pragma unroll
            for (int n8 = 0; n8 < 4; n8++)
                #pragma unroll
                for (int e = 0; e < 4; e++) acc[pl][mf][n8][e] = 0;

    for (int c = 0; c < NCH; c++) {
        MBAR_WAIT(sb + SOFF_BAR + (uint32_t)(c & 3) * 8, (c >> 2) & 1);
        const uint32_t stg = sb + (uint32_t)(c & 3) * STAGE_B;

        #pragma unroll
        for (int kb = 0; kb < 64; kb += 32) {
            uint32_t b[8];
            ldsm_x4(b[0], b[1], b[2], b[3],
                    stg + b_line[0] + ((b_c0[0] + kb) ^ b_xm[0]));
            ldsm_x4(b[4], b[5], b[6], b[7],
                    stg + b_line[1] + ((b_c0[1] + kb) ^ b_xm[1]));
            #pragma unroll
            for (int pl = 0; pl < 2; pl++) {
                #pragma unroll
                for (int mf = 0; mf < 2; mf++) {
                    uint32_t a0, a1, a2, a3;
                    ldsm_x4(a0, a1, a2, a3,
                            stg + a_line[pl][mf] + ((a_c0[pl][mf] + kb) ^ a_xm[pl][mf]));
                    mma_s8(acc[pl][mf][0], a0, a1, a2, a3, b[0], b[1]);
                    mma_s8(acc[pl][mf][1], a0, a1, a2, a3, b[2], b[3]);
                    mma_s8(acc[pl][mf][2], a0, a1, a2, a3, b[4], b[5]);
                    mma_s8(acc[pl][mf][3], a0, a1, a2, a3, b[6], b[7]);
                }
            }
        }
        __syncthreads();                       // stage fully consumed
        if (tid == 0 && c + 4 < NCH) issue(c + 4);
    }

    // ---- combine planes in registers, store h tile to smem ----
    const int g  = lane >> 2;
    const int tg = lane & 3;
    #pragma unroll
    for (int mf = 0; mf < 2; mf++) {
        #pragma unroll
        for (int n8 = 0; n8 < 4; n8++) {
            const int* Ah = acc[0][mf][n8];
            const int* Al = acc[1][mf][n8];
            int row0 = wm * 32 + mf * 16 + g;
            int col  = wn * 32 + n8 * 8 + 2 * tg;
            Csh[row0 * 132 + col]           = (float)Ah[0] * S1_INV + (float)Al[0] * S2_INV;
            Csh[row0 * 132 + col + 1]       = (float)Ah[1] * S1_INV + (float)Al[1] * S2_INV;
            Csh[(row0 + 8) * 132 + col]     = (float)Ah[2] * S1_INV + (float)Al[2] * S2_INV;
            Csh[(row0 + 8) * 132 + col + 1] = (float)Ah[3] * S1_INV + (float)Al[3] * S2_INV;
        }
    }
    __syncthreads();

    // ---- bias + clip + W2 contraction (deterministic partials) ----
    const int row = tid & 127;
    const int q   = tid >> 7;
    float a[OUTF];
    #pragma unroll
    for (int o = 0; o < OUTF; o++) a[o] = 0.0f;

    const int nbeg = q * 32;
    #pragma unroll 4
    for (int n = nbeg; n < nbeg + 32; n++) {
        float h = Csh[row * 132 + n] + b1sh[n];
        h = fminf(1.0f, fmaxf(-1.0f, h));
        #pragma unroll
        for (int o = 0; o < OUTF; o++) a[o] += h * W2sh[o * 128 + n];
    }

    const int slice = blockIdx.x * 4 + q;
    float* dst = &g_part[((size_t)slice * BATCH + m0 + row) * OUTF];
    #pragma unroll
    for (int o = 0; o < OUTF; o++) dst[o] = a[o];
}

// ---------------------------------------------------------------------------
__global__ void reduce_kernel(const float* __restrict__ b2, float* __restrict__ out) {
    int idx = blockIdx.x * blockDim.x + threadIdx.x;
    if (idx >= BATCH * OUTF) return;
    int o = idx % OUTF;
    float s = b2[o];
    #pragma unroll
    for (int p = 0; p < 128; p++)
        s += g_part[(size_t)p * BATCH * OUTF + idx];
    out[idx] = s;
}

// ---------------------------------------------------------------------------
extern "C" void kernel_launch(void* const* d_in, const int* in_sizes, int n_in,
                              void* d_out, int out_size) {
    (void)in_sizes; (void)n_in; (void)out_size;
    const float* x  = (const float*)d_in[0];
    const float* W1 = (const float*)d_in[1];
    const float* b1 = (const float*)d_in[2];
    const float* W2 = (const float*)d_in[3];
    const float* b2 = (const float*)d_in[4];
    float* out = (float*)d_out;

    cudaFuncSetAttribute(gemm1_kernel,
                         cudaFuncAttributeMaxDynamicSharedMemorySize, SMEM_DYN);

    prep_x_kernel<<<(BATCH * KP + 255) / 256, 256>>>(x);
    prep_w_kernel<<<(HID * KP + 255) / 256, 256>>>(W1);
    gemm1_kernel<<<dim3(HID / TNT, BATCH / TMT), 512, SMEM_DYN>>>(b1, W2);
    reduce_kernel<<<(BATCH * OUTF + 255) / 256, 256>>>(b2, out);
}

// round 8
// speedup vs baseline: 1.9758x; 1.1917x over previous
#include <cuda_runtime.h>
#include <cstdint>
#include <cstddef>

#define BATCH 8192
#define INF   784
#define HID   4096
#define OUTF  10
#define KP    832            // 13 chunks of 64
#define NCH   13

#define TMT 128
#define TNT 128
#define NTHR 544             // 16 consumer warps + 1 producer warp

// x = a1/16 + a2/4064 + eps, |eps| <= 1/8128
#define S1_INV 0.0625f
#define S2_INV (1.0f / 4064.0f)

// chunk-major gmem blocks
#define CHUNK_A (BATCH * 64)
#define CHUNK_B (HID * 64)

// SMEM: 4 stages x (Ahi 8K | Alo 8K | B 8K) = 98304
#define STAGE_B  24576u
#define NSTG     4
#define SOFF_QB  69632u              // [4][128][10] f32 quarter partials (reuses stage rgn)
#define SOFF_W2  98304u              // [10][128] f32
#define SOFF_B1  103424u             // [128] f32
#define SOFF_FBAR 103936u            // full[4]
#define SOFF_EBAR 103968u            // empty[4]
#define SMEM_DYN 104960u

// consumer-only named barrier (16 warps = 512 threads)
#define CONS_BAR() asm volatile("bar.sync 1, 512;" ::: "memory")

// ---------------------------------------------------------------------------
__device__ signed char g_A8c[2ull * NCH * CHUNK_A];
__device__ signed char g_S8c[(size_t)NCH * CHUNK_B];
__device__ float g_part[32ull * BATCH * OUTF];

// ---------------------------------------------------------------------------
__device__ __forceinline__ uint32_t smem_u32(const void* p) {
    uint32_t a;
    asm("{ .reg .u64 t; cvta.to.shared.u64 t, %1; cvt.u32.u64 %0, t; }"
        : "=r"(a) : "l"(p));
    return a;
}

__device__ __forceinline__ uint32_t chunk_off(int row, int kk) {
    uint32_t line = (uint32_t)(row >> 1);
    uint32_t col  = (((uint32_t)(row & 1)) << 6) | (uint32_t)kk;
    return (line << 7) | (col ^ ((line & 7u) << 4));
}

__device__ __forceinline__ void ldsm_x4(uint32_t& r0, uint32_t& r1,
                                        uint32_t& r2, uint32_t& r3, uint32_t a) {
    asm volatile("ldmatrix.sync.aligned.m8n8.x4.shared.b16 {%0,%1,%2,%3}, [%4];"
                 : "=r"(r0), "=r"(r1), "=r"(r2), "=r"(r3) : "r"(a));
}

__device__ __forceinline__ void mma_s8(int* d, uint32_t a0, uint32_t a1,
                                       uint32_t a2, uint32_t a3,
                                       uint32_t b0, uint32_t b1) {
    asm volatile(
        "mma.sync.aligned.m16n8k32.row.col.s32.s8.s8.s32 "
        "{%0,%1,%2,%3}, {%4,%5,%6,%7}, {%8,%9}, {%0,%1,%2,%3};"
        : "+r"(d[0]), "+r"(d[1]), "+r"(d[2]), "+r"(d[3])
        : "r"(a0), "r"(a1), "r"(a2), "r"(a3), "r"(b0), "r"(b1));
}

#define MBAR_INIT(a, c) \
    asm volatile("mbarrier.init.shared.b64 [%0], %1;" :: "r"(a), "r"(c) : "memory")
#define MBAR_EXPECT(a, bytes) \
    asm volatile("mbarrier.arrive.expect_tx.shared.b64 _, [%0], %1;" \
                 :: "r"(a), "r"(bytes) : "memory")
#define MBAR_ARRIVE(a) \
    asm volatile("mbarrier.arrive.shared.b64 _, [%0];" :: "r"(a) : "memory")
#define BULK_CP(dst, src, size, mbar) \
    asm volatile("cp.async.bulk.shared::cluster.global.mbarrier::complete_tx::bytes " \
                 "[%0], [%1], %2, [%3];" \
                 :: "r"(dst), "l"(src), "r"(size), "r"(mbar) : "memory")

#define MBAR_WAIT(a, par) do {                                                 \
    uint32_t _m = (a), _p = (par), _d;                                         \
    asm volatile("{\n\t.reg .pred p;\n\t"                                      \
        "mbarrier.try_wait.parity.acquire.cta.shared::cta.b64 p, [%1], %2;\n\t"\
        "selp.b32 %0, 1, 0, p;\n\t}" : "=r"(_d) : "r"(_m), "r"(_p) : "memory");\
    if (!_d) {                                                                 \
        asm volatile("{\n\t.reg .pred P1;\n\t"                                 \
            "WL_%=:\n\t"                                                       \
            "mbarrier.try_wait.parity.acquire.cta.shared::cta.b64 P1, [%0], %1, 0x989680;\n\t" \
            "@P1 bra.uni WD_%=;\n\t"                                           \
            "bra.uni WL_%=;\n\t"                                               \
            "WD_%=:\n\t}" :: "r"(_m), "r"(_p) : "memory");                     \
    }                                                                          \
} while (0)

// ---------------------------------------------------------------------------
__global__ void prep_x_kernel(const float* __restrict__ x) {
    int idx = blockIdx.x * blockDim.x + threadIdx.x;
    if (idx >= BATCH * KP) return;
    int m = idx / KP, k = idx - m * KP;
    float v = (k < INF) ? x[m * INF + k] : 0.0f;
    float a1 = rintf(v * 16.0f);
    float r  = v - a1 * S1_INV;
    float a2 = rintf(r * 4064.0f);
    int c = k >> 6, kk = k & 63;
    size_t o = (size_t)c * CHUNK_A + chunk_off(m, kk);
    g_A8c[o] = (signed char)(int)a1;
    g_A8c[(size_t)NCH * CHUNK_A + o] = (signed char)(int)a2;
}

__global__ void prep_w_kernel(const float* __restrict__ W1) {
    int idx = blockIdx.x * blockDim.x + threadIdx.x;
    if (idx >= HID * KP) return;
    int r = idx / KP, k = idx - r * KP;
    float v = (k < INF) ? W1[r * INF + k] : 0.0f;
    int c = k >> 6, kk = k & 63;
    g_S8c[(size_t)c * CHUNK_B + chunk_off(r, kk)] =
        (signed char)((v > 0.0f) ? 1 : ((v < 0.0f) ? -1 : 0));
}

// ---------------------------------------------------------------------------
// GEMM1: warp-specialized, deadlock-safe barriers.
// Producer warp issues bulk copies then EXITS; consumers use named barrier 1.
// ---------------------------------------------------------------------------
__global__ __launch_bounds__(NTHR, 1)
void gemm1_kernel(const float* __restrict__ b1g, const float* __restrict__ W2g) {
    extern __shared__ unsigned char smem[];
    float* Csh  = (float*)smem;                   // epilogue reuse of stages
    float* Qb   = (float*)(smem + SOFF_QB);       // [4][128][10]
    float* W2sh = (float*)(smem + SOFF_W2);
    float* b1sh = (float*)(smem + SOFF_B1);
    const uint32_t sb = smem_u32(smem);

    const int tid = threadIdx.x;
    const int wid = tid >> 5;
    const int lane = tid & 31;
    const int m0 = blockIdx.y * TMT;
    const int n0 = blockIdx.x * TNT;

    if (tid == 0) {
        #pragma unroll
        for (int s = 0; s < NSTG; s++) {
            MBAR_INIT(sb + SOFF_FBAR + s * 8, 1);    // producer expect_tx
            MBAR_INIT(sb + SOFF_EBAR + s * 8, 16);   // 16 consumer warps
        }
    }
    for (int i = tid; i < OUTF * 128; i += NTHR) {
        int o = i / 128, n = i - o * 128;
        W2sh[o * 128 + n] = W2g[o * HID + n0 + n];
    }
    if (tid < 128) b1sh[tid] = b1g[n0 + tid];
    __syncthreads();   // single, convergent CTA-wide sync

    // ---------------- producer warp: issue everything, then exit ----------
    if (wid == 16) {
        if (lane == 0) {
            for (int c = 0; c < NCH; c++) {
                const int s = c & 3;
                if (c >= NSTG)
                    MBAR_WAIT(sb + SOFF_EBAR + s * 8, ((c >> 2) + 1) & 1);
                const uint32_t stg = sb + (uint32_t)s * STAGE_B;
                const uint32_t mb  = sb + SOFF_FBAR + s * 8;
                MBAR_EXPECT(mb, STAGE_B);
                const signed char* a0 = g_A8c + (size_t)c * CHUNK_A + (size_t)m0 * 64;
                const signed char* a1 = g_A8c + (size_t)(NCH + c) * CHUNK_A + (size_t)m0 * 64;
                const signed char* bb = g_S8c + (size_t)c * CHUNK_B + (size_t)n0 * 64;
                BULK_CP(stg,          a0, 8192u, mb);
                BULK_CP(stg + 8192u,  a1, 8192u, mb);
                BULK_CP(stg + 16384u, bb, 8192u, mb);
            }
        }
        return;
    }

    // ---------------- consumers (512 threads) -----------------------------
    const int wm = wid & 3;
    const int wn = wid >> 2;
    const int l15 = lane & 15;

    uint32_t a_line[2][2], a_xm[2][2], a_c0[2][2];
    #pragma unroll
    for (int pl = 0; pl < 2; pl++)
        #pragma unroll
        for (int mf = 0; mf < 2; mf++) {
            int r = wm * 32 + mf * 16 + l15;
            a_line[pl][mf] = (uint32_t)pl * 8192u + (((uint32_t)r >> 1) << 7);
            a_xm[pl][mf]   = (((uint32_t)(r >> 1) & 7u) << 4);
            a_c0[pl][mf]   = (((uint32_t)r & 1u) << 6) | (((uint32_t)lane >> 4) << 4);
        }
    uint32_t b_line[2], b_xm[2], b_c0[2];
    #pragma unroll
    for (int np = 0; np < 2; np++) {
        int r = wn * 32 + np * 16 + ((lane >> 4) << 3) + (lane & 7);
        b_line[np] = 16384u + (((uint32_t)r >> 1) << 7);
        b_xm[np]   = (((uint32_t)(r >> 1) & 7u) << 4);
        b_c0[np]   = (((uint32_t)r & 1u) << 6) | ((((uint32_t)lane >> 3) & 1u) << 4);
    }

    int acc[2][2][4][4];
    #pragma unroll
    for (int pl = 0; pl < 2; pl++)
        #pragma unroll
        for (int mf = 0; mf < 2; mf++)
            #pragma unroll
            for (int n8 = 0; n8 < 4; n8++)
                #pragma unroll
                for (int e = 0; e < 4; e++) acc[pl][mf][n8][e] = 0;

    for (int c = 0; c < NCH; c++) {
        const int s = c & 3;
        MBAR_WAIT(sb + SOFF_FBAR + s * 8, (c >> 2) & 1);
        const uint32_t stg = sb + (uint32_t)s * STAGE_B;

        #pragma unroll
        for (int kb = 0; kb < 64; kb += 32) {
            uint32_t b[8];
            ldsm_x4(b[0], b[1], b[2], b[3],
                    stg + b_line[0] + ((b_c0[0] + kb) ^ b_xm[0]));
            ldsm_x4(b[4], b[5], b[6], b[7],
                    stg + b_line[1] + ((b_c0[1] + kb) ^ b_xm[1]));
            #pragma unroll
            for (int pl = 0; pl < 2; pl++) {
                #pragma unroll
                for (int mf = 0; mf < 2; mf++) {
                    uint32_t a0, a1, a2, a3;
                    ldsm_x4(a0, a1, a2, a3,
                            stg + a_line[pl][mf] + ((a_c0[pl][mf] + kb) ^ a_xm[pl][mf]));
                    mma_s8(acc[pl][mf][0], a0, a1, a2, a3, b[0], b[1]);
                    mma_s8(acc[pl][mf][1], a0, a1, a2, a3, b[2], b[3]);
                    mma_s8(acc[pl][mf][2], a0, a1, a2, a3, b[4], b[5]);
                    mma_s8(acc[pl][mf][3], a0, a1, a2, a3, b[6], b[7]);
                }
            }
        }
        if (lane == 0) MBAR_ARRIVE(sb + SOFF_EBAR + s * 8);
    }

    CONS_BAR();   // all stages consumed; no bulk copies in flight -> reuse as Csh

    // ---- combine planes in registers, store h tile to smem ----
    {
        const int g  = lane >> 2;
        const int tg = lane & 3;
        #pragma unroll
        for (int mf = 0; mf < 2; mf++) {
            #pragma unroll
            for (int n8 = 0; n8 < 4; n8++) {
                const int* Ah = acc[0][mf][n8];
                const int* Al = acc[1][mf][n8];
                int row0 = wm * 32 + mf * 16 + g;
                int col  = wn * 32 + n8 * 8 + 2 * tg;
                Csh[row0 * 132 + col]           = (float)Ah[0] * S1_INV + (float)Al[0] * S2_INV;
                Csh[row0 * 132 + col + 1]       = (float)Ah[1] * S1_INV + (float)Al[1] * S2_INV;
                Csh[(row0 + 8) * 132 + col]     = (float)Ah[2] * S1_INV + (float)Al[2] * S2_INV;
                Csh[(row0 + 8) * 132 + col + 1] = (float)Ah[3] * S1_INV + (float)Al[3] * S2_INV;
            }
        }
    }
    CONS_BAR();

    // ---- bias + clip + W2 contraction; quarter partials in smem ----
    {
        const int row = tid & 127;
        const int q   = tid >> 7;          // 0..3
        float a[OUTF];
        #pragma unroll
        for (int o = 0; o < OUTF; o++) a[o] = 0.0f;

        const int nbeg = q * 32;
        #pragma unroll 4
        for (int n = nbeg; n < nbeg + 32; n++) {
            float h = Csh[row * 132 + n] + b1sh[n];
            h = fminf(1.0f, fmaxf(-1.0f, h));
            #pragma unroll
            for (int o = 0; o < OUTF; o++) a[o] += h * W2sh[o * 128 + n];
        }
        #pragma unroll
        for (int o = 0; o < OUTF; o++)
            Qb[(q * 128 + row) * OUTF + o] = a[o];
    }
    CONS_BAR();

    // ---- combine quarters, write one slice per CTA column ----
    for (int i = tid; i < 128 * OUTF; i += 512) {
        float s = Qb[i] + Qb[128 * OUTF + i] + Qb[256 * OUTF + i] + Qb[384 * OUTF + i];
        int row = i / OUTF, o = i - row * OUTF;
        g_part[((size_t)blockIdx.x * BATCH + m0 + row) * OUTF + o] = s;
    }
}

// ---------------------------------------------------------------------------
__global__ void reduce_kernel(const float* __restrict__ b2, float* __restrict__ out) {
    int idx = blockIdx.x * blockDim.x + threadIdx.x;
    if (idx >= BATCH * OUTF) return;
    int o = idx % OUTF;
    float s = b2[o];
    #pragma unroll
    for (int p = 0; p < 32; p++)
        s += g_part[(size_t)p * BATCH * OUTF + idx];
    out[idx] = s;
}

// ---------------------------------------------------------------------------
extern "C" void kernel_launch(void* const* d_in, const int* in_sizes, int n_in,
                              void* d_out, int out_size) {
    (void)in_sizes; (void)n_in; (void)out_size;
    const float* x  = (const float*)d_in[0];
    const float* W1 = (const float*)d_in[1];
    const float* b1 = (const float*)d_in[2];
    const float* W2 = (const float*)d_in[3];
    const float* b2 = (const float*)d_in[4];
    float* out = (float*)d_out;

    cudaFuncSetAttribute(gemm1_kernel,
                         cudaFuncAttributeMaxDynamicSharedMemorySize, SMEM_DYN);

    prep_x_kernel<<<(BATCH * KP + 255) / 256, 256>>>(x);
    prep_w_kernel<<<(HID * KP + 255) / 256, 256>>>(W1);
    gemm1_kernel<<<dim3(HID / TNT, BATCH / TMT), NTHR, SMEM_DYN>>>(b1, W2);
    reduce_kernel<<<(BATCH * OUTF + 255) / 256, 256>>>(b2, out);
}